// round 1
// baseline (speedup 1.0000x reference)
#include <cuda_runtime.h>

// 2x trilinear upsample (TF v1 asymmetric coords, scale = 0.5 per axis).
// Input : [B=2, H=96, W=96, D=48, C=32] f32, channels-last contiguous.
// Output: [B=2, 192, 192, 96, 32] f32.
//
// Even output coord -> copy; odd -> average of i and min(i+1, last).
// One thread = one input voxel x one float4 channel group; it loads the
// 2x2x2 input corner neighborhood (8 float4 loads) and writes the 2x2x2
// output block (8 float4 stores). 1 load + 1 store per output float4.

#define IN_H 96
#define IN_W 96
#define IN_D 48
#define C4   8          // 32 channels = 8 float4
#define OUT_H 192
#define OUT_W 192
#define OUT_D 96

__device__ __forceinline__ float4 avg4(float4 a, float4 b) {
    return make_float4(0.5f * (a.x + b.x),
                       0.5f * (a.y + b.y),
                       0.5f * (a.z + b.z),
                       0.5f * (a.w + b.w));
}

__global__ __launch_bounds__(256)
void upsample3d_2x_kernel(const float4* __restrict__ in,
                          float4* __restrict__ out) {
    int tid = blockIdx.x * blockDim.x + threadIdx.x;
    // total threads = B * H * W * D * C4 = 2*96*96*48*8 = 7,077,888 (exact grid)

    int c4 = tid & (C4 - 1);
    int t  = tid >> 3;          // C4 == 8
    int d  = t % IN_D;  t /= IN_D;
    int w  = t % IN_W;  t /= IN_W;
    int h  = t % IN_H;
    int b  = t / IN_H;

    int h1 = min(h + 1, IN_H - 1);
    int w1 = min(w + 1, IN_W - 1);
    int d1 = min(d + 1, IN_D - 1);

    // input float4 index
    auto iidx = [&](int hh, int ww, int dd) {
        return (((b * IN_H + hh) * IN_W + ww) * IN_D + dd) * C4 + c4;
    };

    float4 v000 = in[iidx(h,  w,  d )];
    float4 v001 = in[iidx(h,  w,  d1)];
    float4 v010 = in[iidx(h,  w1, d )];
    float4 v011 = in[iidx(h,  w1, d1)];
    float4 v100 = in[iidx(h1, w,  d )];
    float4 v101 = in[iidx(h1, w,  d1)];
    float4 v110 = in[iidx(h1, w1, d )];
    float4 v111 = in[iidx(h1, w1, d1)];

    // D-direction midpoints
    float4 m00 = avg4(v000, v001);
    float4 m01 = avg4(v010, v011);
    float4 m10 = avg4(v100, v101);
    float4 m11 = avg4(v110, v111);

    int oh = 2 * h, ow = 2 * w, od = 2 * d;
    auto oidx = [&](int hh, int ww, int dd) {
        return (((b * OUT_H + hh) * OUT_W + ww) * OUT_D + dd) * C4 + c4;
    };

    // pd = 0 plane (corners at d)
    float4 p01 = avg4(v000, v010);               // (ph=0, pw=1)
    float4 p10 = avg4(v000, v100);               // (ph=1, pw=0)
    float4 p11 = avg4(p01, avg4(v100, v110));    // (ph=1, pw=1)
    out[oidx(oh,     ow,     od)] = v000;
    out[oidx(oh,     ow + 1, od)] = p01;
    out[oidx(oh + 1, ow,     od)] = p10;
    out[oidx(oh + 1, ow + 1, od)] = p11;

    // pd = 1 plane (corners at d midpoints)
    float4 q01 = avg4(m00, m01);
    float4 q10 = avg4(m00, m10);
    float4 q11 = avg4(q01, avg4(m10, m11));
    out[oidx(oh,     ow,     od + 1)] = m00;
    out[oidx(oh,     ow + 1, od + 1)] = q01;
    out[oidx(oh + 1, ow,     od + 1)] = q10;
    out[oidx(oh + 1, ow + 1, od + 1)] = q11;
}

extern "C" void kernel_launch(void* const* d_in, const int* in_sizes, int n_in,
                              void* d_out, int out_size) {
    const float4* in  = (const float4*)d_in[0];
    float4*       out = (float4*)d_out;

    const int total_threads = 2 * IN_H * IN_W * IN_D * C4;  // 7,077,888
    const int block = 256;
    const int grid  = total_threads / block;                 // 27,648 exact

    upsample3d_2x_kernel<<<grid, block>>>(in, out);
}